// round 14
// baseline (speedup 1.0000x reference)
#include <cuda_runtime.h>
#include <cuda_bf16.h>
#include <cstdint>
#include <math.h>

#define D     512
#define NE    8192
#define NMAX  32768
#define BETA  0.25f

#define BM      256
#define BN      128
#define NTILES  (NE / BN)          // 64
#define TOTALG  (NTILES * 4)       // 256 chunks of K=128 (s8)
#define NTHR    512

// ---------------- device scratch ----------------
__device__ int8_t g_z8[(size_t)NMAX * D];
__device__ int8_t g_e8[(size_t)NE * D];          // quantized PRE-NORMALIZED emb
__device__ float    g_inv[NE];
__device__ unsigned g_emax_bits;
__device__ float    g_counts[NE];
__device__ int      g_idx[NMAX];
__device__ int      g_cand[(size_t)NMAX * 8];
__device__ float    g_loss;

// ---------------- PTX helpers ----------------
__device__ __forceinline__ uint32_t smem_u32(const void* p) {
    uint32_t a;
    asm("{ .reg .u64 t; cvta.to.shared.u64 t, %1; cvt.u32.u64 %0, t; }" : "=r"(a) : "l"(p));
    return a;
}
#define CP16(dst, src) \
    asm volatile("cp.async.cg.shared.global [%0], [%1], 16;" :: "r"(dst), "l"(src) : "memory")
#define CP_COMMIT() asm volatile("cp.async.commit_group;" ::: "memory")
#define CP_WAIT(n)  asm volatile("cp.async.wait_group %0;" :: "n"(n) : "memory")

__device__ __forceinline__ void ldsm_x4(uint32_t& r0, uint32_t& r1, uint32_t& r2, uint32_t& r3,
                                        uint32_t addr) {
    asm volatile("ldmatrix.sync.aligned.m8n8.x4.shared.b16 {%0,%1,%2,%3}, [%4];"
                 : "=r"(r0), "=r"(r1), "=r"(r2), "=r"(r3) : "r"(addr));
}
__device__ __forceinline__ void mma_s8(int* d, uint32_t a0, uint32_t a1, uint32_t a2,
                                       uint32_t a3, uint32_t b0, uint32_t b1) {
    asm volatile("mma.sync.aligned.m16n8k32.row.col.s32.s8.s8.s32 "
                 "{%0,%1,%2,%3}, {%4,%5,%6,%7}, {%8,%9}, {%0,%1,%2,%3};"
                 : "+r"(d[0]), "+r"(d[1]), "+r"(d[2]), "+r"(d[3])
                 : "r"(a0), "r"(a1), "r"(a2), "r"(a3), "r"(b0), "r"(b1));
}

__device__ __forceinline__ int8_t q8(float v, float scale) {
    int q = __float2int_rn(v * scale);
    q = q > 127 ? 127 : (q < -127 ? -127 : q);
    return (int8_t)q;
}

// ---------------- small kernels ----------------
__global__ void zero_kernel() {
    int i = blockIdx.x * blockDim.x + threadIdx.x;
    if (i < NE) g_counts[i] = 0.0f;
    if (i == 0) { g_loss = 0.0f; g_emax_bits = 0u; }
}

// pass 1: per-row inv norm + global absmax of normalized components
__global__ void embprep1_kernel(const float* __restrict__ emb) {
    int e = blockIdx.x;
    int t = threadIdx.x;   // 128 threads, 4 floats each
    float4 v = ((const float4*)(emb + (size_t)e * D))[t];
    float ss = v.x * v.x + v.y * v.y + v.z * v.z + v.w * v.w;
    float am = fmaxf(fmaxf(fabsf(v.x), fabsf(v.y)), fmaxf(fabsf(v.z), fabsf(v.w)));
    for (int o = 16; o; o >>= 1) {
        ss += __shfl_down_sync(0xffffffffu, ss, o);
        am = fmaxf(am, __shfl_down_sync(0xffffffffu, am, o));
    }
    __shared__ float s[4], m[4];
    if ((t & 31) == 0) { s[t >> 5] = ss; m[t >> 5] = am; }
    __syncthreads();
    if (t == 0) {
        float tot = s[0] + s[1] + s[2] + s[3];
        float amx = fmaxf(fmaxf(m[0], m[1]), fmaxf(m[2], m[3]));
        float inv = 1.0f / fmaxf(sqrtf(tot), 1e-12f);
        g_inv[e] = inv;
        atomicMax(&g_emax_bits, __float_as_uint(amx * inv));
    }
}

// pass 2: quantize normalized emb rows with the global scale
__global__ void embprep2_kernel(const float* __restrict__ emb) {
    int e = blockIdx.x;
    int t = threadIdx.x;
    float scale = 127.0f / fmaxf(__uint_as_float(g_emax_bits), 1e-20f);
    float inv = g_inv[e];
    float4 v = ((const float4*)(emb + (size_t)e * D))[t];
    char4 q;
    q.x = q8(v.x * inv, scale); q.y = q8(v.y * inv, scale);
    q.z = q8(v.z * inv, scale); q.w = q8(v.w * inv, scale);
    ((char4*)(g_z8 + 0, g_e8 + (size_t)e * D))[t] = q;   // g_e8 row
}

// per-row quantize z (row scale is argmax-invariant)
__global__ void zquant_kernel(const float* __restrict__ z) {
    int n = blockIdx.x;
    int t = threadIdx.x;   // 128 threads
    float4 v = ((const float4*)(z + (size_t)n * D))[t];
    float am = fmaxf(fmaxf(fabsf(v.x), fabsf(v.y)), fmaxf(fabsf(v.z), fabsf(v.w)));
    for (int o = 16; o; o >>= 1) am = fmaxf(am, __shfl_down_sync(0xffffffffu, am, o));
    __shared__ float m[4];
    __shared__ float sm;
    if ((t & 31) == 0) m[t >> 5] = am;
    __syncthreads();
    if (t == 0) sm = fmaxf(fmaxf(m[0], m[1]), fmaxf(m[2], m[3]));
    __syncthreads();
    float scale = 127.0f / fmaxf(sm, 1e-20f);
    char4 q;
    q.x = q8(v.x, scale); q.y = q8(v.y, scale);
    q.z = q8(v.z, scale); q.w = q8(v.w, scale);
    ((char4*)(g_z8 + (size_t)n * D))[t] = q;
}

// ---------------- int8 MMA GEMM (K=512) + fused top-4 argmax ----------------
// 128 CTAs x 512 threads (16 warps, grid 8x2). CTA = 256-row strip, 64 N-tiles.
// Chunk = K=128 s8 elements (128B/row) -> byte layout identical to bf16 K=64.
// s32 scores; emb pre-normalized+globally scaled, z per-row scaled -> argmax ok.
#define ABYTES  (BM * 128)         // 32768
#define BBYTES  (BN * 128)         // 16384
#define STAGE   (ABYTES + BBYTES)  // 49152
#define NSTG    3
#define SMEM_SZ (NSTG * STAGE)     // 147456

extern __shared__ char smem_raw[];

struct Top4i { int v[4]; int i[4]; };

__device__ __forceinline__ void t4_update(Top4i& t, int s, int c) {
    if (s <= t.v[3]) return;
    if (s > t.v[1]) {
        if (s > t.v[0]) {
            t.v[3] = t.v[2]; t.i[3] = t.i[2];
            t.v[2] = t.v[1]; t.i[2] = t.i[1];
            t.v[1] = t.v[0]; t.i[1] = t.i[0];
            t.v[0] = s;      t.i[0] = c;
        } else {
            t.v[3] = t.v[2]; t.i[3] = t.i[2];
            t.v[2] = t.v[1]; t.i[2] = t.i[1];
            t.v[1] = s;      t.i[1] = c;
        }
    } else {
        if (s > t.v[2]) {
            t.v[3] = t.v[2]; t.i[3] = t.i[2];
            t.v[2] = s;      t.i[2] = c;
        } else {
            t.v[3] = s;      t.i[3] = c;
        }
    }
}

__device__ __forceinline__ void load_chunk(uint32_t sb, int g, int stage, int row0, int tid) {
    const int kl = (g & 3) * 128;              // byte == element offset (s8)
    const int e0 = (g >> 2) * BN;
    const uint32_t ab = sb + stage * STAGE;
    const uint32_t bb = ab + ABYTES;
#pragma unroll
    for (int it = 0; it < 4; it++) {           // A: 2048 x 16B
        int u = tid + it * NTHR;
        int m2 = u >> 3, q = u & 7;
        uint32_t dst = ab + m2 * 128 + ((q ^ (m2 & 7)) << 4);
        CP16(dst, g_z8 + (size_t)(row0 + m2) * D + kl + q * 16);
    }
#pragma unroll
    for (int it = 0; it < 2; it++) {           // B: 1024 x 16B
        int u = tid + it * NTHR;
        int n = u >> 3, q = u & 7;
        uint32_t dst = bb + n * 128 + ((q ^ (n & 7)) << 4);
        CP16(dst, g_e8 + (size_t)(e0 + n) * D + kl + q * 16);
    }
    CP_COMMIT();
}

__global__ void __launch_bounds__(NTHR, 1) mma_argmax_kernel() {
    const uint32_t sb = smem_u32(smem_raw);
    const int tid  = threadIdx.x;
    const int wid  = tid >> 5;                 // 0..15
    const int lane = tid & 31;
    const int row0 = blockIdx.x * BM;
    const int wy   = wid >> 1;
    const int wx   = wid & 1;
    const int wrow = wy * 32;
    const int wcol = wx * 64;

    const int a_lrow = (lane & 15);
    const int a_kx   = (lane >> 4);
    const int b_rowb = ((lane >> 4) << 3) + (lane & 7);
    const int b_kx   = (lane >> 3) & 1;

    int acc[2][8][4];
#pragma unroll
    for (int af = 0; af < 2; af++)
#pragma unroll
        for (int f = 0; f < 8; f++)
#pragma unroll
            for (int j = 0; j < 4; j++) acc[af][f][j] = 0;

    Top4i tp[2][2];
#pragma unroll
    for (int af = 0; af < 2; af++)
#pragma unroll
        for (int rh = 0; rh < 2; rh++)
#pragma unroll
            for (int k = 0; k < 4; k++) { tp[af][rh].v[k] = (int)0x80000000; tp[af][rh].i[k] = 0; }

    load_chunk(sb, 0, 0, row0, tid);
    load_chunk(sb, 1, 1, row0, tid);

    int st = 0;
    for (int g = 0; g < TOTALG; g++) {
        if (g + 1 < TOTALG) CP_WAIT(1); else CP_WAIT(0);
        __syncthreads();

        if (g + 2 < TOTALG) {
            int st2 = st + 2; if (st2 >= NSTG) st2 -= NSTG;
            load_chunk(sb, g + 2, st2, row0, tid);
        }

        const uint32_t ab = sb + st * STAGE;
        const uint32_t bb = ab + ABYTES;
#pragma unroll
        for (int s = 0; s < 4; s++) {          // 4 k-steps of K=32 s8
            uint32_t a[2][4];
#pragma unroll
            for (int af = 0; af < 2; af++) {
                int row = wrow + af * 16 + a_lrow;
                int ku  = s * 2 + a_kx;
                uint32_t addr = ab + row * 128 + ((ku ^ (row & 7)) << 4);
                ldsm_x4(a[af][0], a[af][1], a[af][2], a[af][3], addr);
            }
#pragma unroll
            for (int gn = 0; gn < 4; gn++) {
                uint32_t b0, b1, b2, b3;
                int n  = wcol + gn * 16 + b_rowb;
                int ku = s * 2 + b_kx;
                uint32_t addr = bb + n * 128 + ((ku ^ (n & 7)) << 4);
                ldsm_x4(b0, b1, b2, b3, addr);
                mma_s8(acc[0][gn * 2],     a[0][0], a[0][1], a[0][2], a[0][3], b0, b1);
                mma_s8(acc[0][gn * 2 + 1], a[0][0], a[0][1], a[0][2], a[0][3], b2, b3);
                mma_s8(acc[1][gn * 2],     a[1][0], a[1][1], a[1][2], a[1][3], b0, b1);
                mma_s8(acc[1][gn * 2 + 1], a[1][0], a[1][1], a[1][2], a[1][3], b2, b3);
            }
        }

        if ((g & 3) == 3) {
            // tile epilogue: integer scores, no loads
            const int e0 = (g >> 2) * BN;
            const int c2 = (lane & 3) * 2;
#pragma unroll
            for (int af = 0; af < 2; af++)
#pragma unroll
                for (int f = 0; f < 8; f++) {
                    int col0 = e0 + wcol + f * 8 + c2;
                    t4_update(tp[af][0], acc[af][f][0], col0);
                    t4_update(tp[af][0], acc[af][f][1], col0 + 1);
                    t4_update(tp[af][1], acc[af][f][2], col0);
                    t4_update(tp[af][1], acc[af][f][3], col0 + 1);
#pragma unroll
                    for (int j = 0; j < 4; j++) acc[af][f][j] = 0;
                }
        }
        st = st + 1; if (st >= NSTG) st -= NSTG;
    }

    // merge top-4 across the 4 lanes sharing each row (within this warp's half)
#pragma unroll
    for (int af = 0; af < 2; af++)
#pragma unroll
        for (int rh = 0; rh < 2; rh++) {
#pragma unroll
            for (int o = 1; o < 4; o <<= 1) {
                int ov[4], oi[4];
#pragma unroll
                for (int k = 0; k < 4; k++) {
                    ov[k] = __shfl_xor_sync(0xffffffffu, tp[af][rh].v[k], o);
                    oi[k] = __shfl_xor_sync(0xffffffffu, tp[af][rh].i[k], o);
                }
#pragma unroll
                for (int k = 0; k < 4; k++) t4_update(tp[af][rh], ov[k], oi[k]);
            }
        }
    if ((lane & 3) == 0) {
#pragma unroll
        for (int af = 0; af < 2; af++)
#pragma unroll
            for (int rh = 0; rh < 2; rh++) {
                int r = row0 + wrow + af * 16 + rh * 8 + (lane >> 2);
#pragma unroll
                for (int k = 0; k < 4; k++) g_cand[r * 8 + wx * 4 + k] = tp[af][rh].i[k];
            }
    }
}

// ---------------- exact fp32 re-score of 8 candidates ----------------
__global__ void fixup_kernel(const float* __restrict__ z, const float* __restrict__ emb) {
    int row  = (blockIdx.x * blockDim.x + threadIdx.x) >> 5;
    int lane = threadIdx.x & 31;
    const float4* zr = (const float4*)(z + (size_t)row * D);
    float4 zf[4];
#pragma unroll
    for (int j = 0; j < 4; j++) zf[j] = zr[lane + j * 32];

    float bv = -INFINITY;
    int   bi = 0x7fffffff;
#pragma unroll
    for (int c = 0; c < 8; c++) {
        int e = g_cand[row * 8 + c];
        const float4* er = (const float4*)(emb + (size_t)e * D);
        float d = 0.0f;
#pragma unroll
        for (int j = 0; j < 4; j++) {
            float4 ev = er[lane + j * 32];
            d += zf[j].x * ev.x + zf[j].y * ev.y + zf[j].z * ev.z + zf[j].w * ev.w;
        }
        for (int o = 16; o; o >>= 1) d += __shfl_down_sync(0xffffffffu, d, o);
        if (lane == 0) {
            float s = d * g_inv[e];
            if (s > bv || (s == bv && e < bi)) { bv = s; bi = e; }
        }
    }
    if (lane == 0) g_idx[row] = bi;
}

// ---------------- gather + z_q_st + loss + counts + idx out ----------------
__global__ void gather_kernel(const float* __restrict__ z,
                              const float* __restrict__ emb,
                              float* __restrict__ out_zq,
                              float* __restrict__ out_idx) {
    __shared__ float sred[4];
    __shared__ float sbc;
    int n = blockIdx.x;
    int t = threadIdx.x;
    int e = g_idx[n];
    float inv_e = g_inv[e];

    float4 zv = ((const float4*)(z + (size_t)n * D))[t];
    float ss = zv.x * zv.x + zv.y * zv.y + zv.z * zv.z + zv.w * zv.w;
    for (int o = 16; o; o >>= 1) ss += __shfl_down_sync(0xffffffffu, ss, o);
    if ((t & 31) == 0) sred[t >> 5] = ss;
    __syncthreads();
    if (t == 0) sbc = sred[0] + sred[1] + sred[2] + sred[3];
    __syncthreads();
    float zinv = 1.0f / fmaxf(sqrtf(sbc), 1e-12f);

    float4 q = ((const float4*)(emb + (size_t)e * D))[t];
    q.x *= inv_e; q.y *= inv_e; q.z *= inv_e; q.w *= inv_e;

    float* o = out_zq + (size_t)n * D + t * 4;
    o[0] = q.x; o[1] = q.y; o[2] = q.z; o[3] = q.w;

    float dx = q.x - zv.x * zinv;
    float dy = q.y - zv.y * zinv;
    float dz = q.z - zv.z * zinv;
    float dw = q.w - zv.w * zinv;
    float ls = dx * dx + dy * dy + dz * dz + dw * dw;
    for (int o2 = 16; o2; o2 >>= 1) ls += __shfl_down_sync(0xffffffffu, ls, o2);
    if ((t & 31) == 0) sred[t >> 5] = ls;
    __syncthreads();
    if (t == 0) {
        atomicAdd(&g_loss, sred[0] + sred[1] + sred[2] + sred[3]);
        atomicAdd(&g_counts[e], 1.0f);
        out_idx[n] = (float)e;
    }
}

__global__ void finalize_kernel(float* __restrict__ out, int N) {
    __shared__ float sh[256];
    float h = 0.0f;
    float invN = 1.0f / (float)N;
    for (int i = threadIdx.x; i < NE; i += 256) {
        float p = g_counts[i] * invN;
        h -= p * logf(p + 1e-10f);
    }
    sh[threadIdx.x] = h;
    __syncthreads();
    for (int s = 128; s; s >>= 1) {
        if (threadIdx.x < s) sh[threadIdx.x] += sh[threadIdx.x + s];
        __syncthreads();
    }
    if (threadIdx.x == 0) {
        out[0] = g_loss * (1.0f + BETA) / ((float)N * (float)D);
        out[1 + (size_t)N * D + (size_t)N] = expf(sh[0]);
    }
}

// ---------------- launch ----------------
extern "C" void kernel_launch(void* const* d_in, const int* in_sizes, int n_in,
                              void* d_out, int out_size) {
    const float* z   = (const float*)d_in[0];
    const float* emb = (const float*)d_in[1];
    float* out = (float*)d_out;

    int ND = in_sizes[0];
    int N  = ND / D;            // 32768

    cudaFuncSetAttribute(mma_argmax_kernel,
                         cudaFuncAttributeMaxDynamicSharedMemorySize, SMEM_SZ);

    zero_kernel<<<(NE + 255) / 256, 256>>>();
    embprep1_kernel<<<NE, 128>>>(emb);
    embprep2_kernel<<<NE, 128>>>(emb);
    zquant_kernel<<<N, 128>>>(z);
    mma_argmax_kernel<<<N / BM, NTHR, SMEM_SZ>>>();
    fixup_kernel<<<N / 8, 256>>>(z, emb);
    // output layout (tuple order, all as float32):
    // [0] loss | [1 .. 1+N*D) z_q_st | [1+N*D .. 1+N*D+N) idx | [last] perplexity
    gather_kernel<<<N, 128>>>(z, emb, out + 1, out + 1 + (size_t)ND);
    finalize_kernel<<<1, 256>>>(out, N);
}

// round 15
// speedup vs baseline: 2.2245x; 2.2245x over previous
#include <cuda_runtime.h>
#include <cuda_fp16.h>
#include <cstdint>
#include <math.h>

#define D     512
#define NE    8192
#define NMAX  32768
#define BETA  0.25f

#define BM      256
#define BN      128
#define BK      64
#define NTILES  (NE / BN)          // 64
#define TOTALG  (NTILES * 8)       // 512 chunks of K=64

// ---------------- device scratch ----------------
__device__ __half g_zh[(size_t)NMAX * D];
__device__ __half g_eh[(size_t)NE * D];          // PRE-NORMALIZED emb (fp16)
__device__ float g_inv[NE];
__device__ float g_counts[NE];
__device__ int   g_idx[NMAX];
__device__ int   g_cand[(size_t)NMAX * 4];
__device__ float g_loss;

// ---------------- PTX helpers ----------------
__device__ __forceinline__ uint32_t smem_u32(const void* p) {
    uint32_t a;
    asm("{ .reg .u64 t; cvta.to.shared.u64 t, %1; cvt.u32.u64 %0, t; }" : "=r"(a) : "l"(p));
    return a;
}
#define CP16(dst, src) \
    asm volatile("cp.async.cg.shared.global [%0], [%1], 16;" :: "r"(dst), "l"(src) : "memory")
#define CP_COMMIT() asm volatile("cp.async.commit_group;" ::: "memory")
#define CP_WAIT(n)  asm volatile("cp.async.wait_group %0;" :: "n"(n) : "memory")

__device__ __forceinline__ void ldsm_x4(uint32_t& r0, uint32_t& r1, uint32_t& r2, uint32_t& r3,
                                        uint32_t addr) {
    asm volatile("ldmatrix.sync.aligned.m8n8.x4.shared.b16 {%0,%1,%2,%3}, [%4];"
                 : "=r"(r0), "=r"(r1), "=r"(r2), "=r"(r3) : "r"(addr));
}
// fp16-accumulate HMMA: D,C are 2 packed half2 regs (row r cols c,c+1 | row r+8)
__device__ __forceinline__ void mma_f16a(uint32_t* d, uint32_t a0, uint32_t a1, uint32_t a2,
                                         uint32_t a3, uint32_t b0, uint32_t b1) {
    asm volatile("mma.sync.aligned.m16n8k16.row.col.f16.f16.f16.f16 "
                 "{%0,%1}, {%2,%3,%4,%5}, {%6,%7}, {%0,%1};"
                 : "+r"(d[0]), "+r"(d[1])
                 : "r"(a0), "r"(a1), "r"(a2), "r"(a3), "r"(b0), "r"(b1));
}

// ---------------- small kernels ----------------
__global__ void zero_kernel() {
    int i = blockIdx.x * blockDim.x + threadIdx.x;
    if (i < NE) g_counts[i] = 0.0f;
    if (i == 0) g_loss = 0.0f;
}

// one block per emb row: compute inv norm, store it, write normalized fp16 row
__global__ void embprep_kernel(const float* __restrict__ emb) {
    int e = blockIdx.x;
    int t = threadIdx.x;   // 128 threads, 4 floats each
    float4 v = ((const float4*)(emb + (size_t)e * D))[t];
    float ss = v.x * v.x + v.y * v.y + v.z * v.z + v.w * v.w;
    for (int o = 16; o; o >>= 1) ss += __shfl_down_sync(0xffffffffu, ss, o);
    __shared__ float s[4];
    __shared__ float sinv;
    if ((t & 31) == 0) s[t >> 5] = ss;
    __syncthreads();
    if (t == 0) {
        float tot = s[0] + s[1] + s[2] + s[3];
        float inv = 1.0f / fmaxf(sqrtf(tot), 1e-12f);
        g_inv[e] = inv;
        sinv = inv;
    }
    __syncthreads();
    float inv = sinv;
    __half2* dst = (__half2*)g_eh + (size_t)e * (D / 2) + t * 2;
    dst[0] = __floats2half2_rn(v.x * inv, v.y * inv);
    dst[1] = __floats2half2_rn(v.z * inv, v.w * inv);
}

__global__ void cvt_z_kernel(const float* __restrict__ z) {
    size_t i = (size_t)blockIdx.x * blockDim.x + threadIdx.x;
    float4 v = ((const float4*)z)[i];
    __half2* dst = (__half2*)g_zh;
    dst[i * 2]     = __floats2half2_rn(v.x, v.y);
    dst[i * 2 + 1] = __floats2half2_rn(v.z, v.w);
}

// ---------------- HMMA GEMM (fp16, fp16-acc, K=512) + fused top-4 argmax ----
// 128 CTAs x 256 threads (8 warps). CTA = 256-row strip, loops 64 N-tiles.
// Warp w: rows w*32..w*32+31 x all 128 tile cols. B pre-normalized -> acc IS
// the cosine score. 3-stage cp.async pipeline, ONE __syncthreads per chunk.
#define ABYTES  (BM * BK * 2)      // 32768
#define BBYTES  (BN * BK * 2)      // 16384
#define STAGE   (ABYTES + BBYTES)  // 49152
#define NSTG    3
#define SMEM_SZ (NSTG * STAGE)     // 147456

extern __shared__ char smem_raw[];

struct Top4 { float v[4]; int i[4]; };

__device__ __forceinline__ void t4_update(Top4& t, float s, int c) {
    if (s <= t.v[3]) return;
    if (s > t.v[1]) {
        if (s > t.v[0]) {
            t.v[3] = t.v[2]; t.i[3] = t.i[2];
            t.v[2] = t.v[1]; t.i[2] = t.i[1];
            t.v[1] = t.v[0]; t.i[1] = t.i[0];
            t.v[0] = s;      t.i[0] = c;
        } else {
            t.v[3] = t.v[2]; t.i[3] = t.i[2];
            t.v[2] = t.v[1]; t.i[2] = t.i[1];
            t.v[1] = s;      t.i[1] = c;
        }
    } else {
        if (s > t.v[2]) {
            t.v[3] = t.v[2]; t.i[3] = t.i[2];
            t.v[2] = s;      t.i[2] = c;
        } else {
            t.v[3] = s;      t.i[3] = c;
        }
    }
}

__device__ __forceinline__ void load_chunk(uint32_t sb, int g, int stage, int row0, int tid) {
    const int kl = (g & 7) * BK;
    const int e0 = (g >> 3) * BN;
    const uint32_t ab = sb + stage * STAGE;
    const uint32_t bb = ab + ABYTES;
#pragma unroll
    for (int it = 0; it < 8; it++) {           // A: 2048 x 16B
        int u = tid + it * 256;
        int m = u >> 3, q = u & 7;
        uint32_t dst = ab + m * 128 + ((q ^ (m & 7)) << 4);
        CP16(dst, g_zh + (size_t)(row0 + m) * D + kl + q * 8);
    }
#pragma unroll
    for (int it = 0; it < 4; it++) {           // B: 1024 x 16B
        int u = tid + it * 256;
        int n = u >> 3, q = u & 7;
        uint32_t dst = bb + n * 128 + ((q ^ (n & 7)) << 4);
        CP16(dst, g_eh + (size_t)(e0 + n) * D + kl + q * 8);
    }
    CP_COMMIT();
}

__global__ void __launch_bounds__(256, 1) mma_argmax_kernel() {
    const uint32_t sb = smem_u32(smem_raw);
    const int tid  = threadIdx.x;
    const int wid  = tid >> 5;                 // 0..7
    const int lane = tid & 31;
    const int row0 = blockIdx.x * BM;
    const int wrow = wid * 32;

    const int a_lrow = (lane & 15);
    const int a_kx   = (lane >> 4);
    const int b_rowb = ((lane >> 4) << 3) + (lane & 7);
    const int b_kx   = (lane >> 3) & 1;

    // acc[af][f][rh]: packed half2 (cols c,c+1), rh = row-half (r / r+8)
    uint32_t acc[2][16][2];
#pragma unroll
    for (int af = 0; af < 2; af++)
#pragma unroll
        for (int f = 0; f < 16; f++) { acc[af][f][0] = 0u; acc[af][f][1] = 0u; }

    Top4 tp[2][2];
#pragma unroll
    for (int af = 0; af < 2; af++)
#pragma unroll
        for (int rh = 0; rh < 2; rh++)
#pragma unroll
            for (int k = 0; k < 4; k++) { tp[af][rh].v[k] = -INFINITY; tp[af][rh].i[k] = 0; }

    load_chunk(sb, 0, 0, row0, tid);
    load_chunk(sb, 1, 1, row0, tid);

    int st = 0;
    for (int g = 0; g < TOTALG; g++) {
        if (g + 1 < TOTALG) CP_WAIT(1); else CP_WAIT(0);
        __syncthreads();   // all warps done reading stage (g-1)%3; chunk g visible

        if (g + 2 < TOTALG) {
            int st2 = st + 2; if (st2 >= NSTG) st2 -= NSTG;
            load_chunk(sb, g + 2, st2, row0, tid);
        }

        const uint32_t ab = sb + st * STAGE;
        const uint32_t bb = ab + ABYTES;
#pragma unroll
        for (int s = 0; s < 4; s++) {
            uint32_t a[2][4];
#pragma unroll
            for (int af = 0; af < 2; af++) {
                int row = wrow + af * 16 + a_lrow;
                int ku  = s * 2 + a_kx;
                uint32_t addr = ab + row * 128 + ((ku ^ (row & 7)) << 4);
                ldsm_x4(a[af][0], a[af][1], a[af][2], a[af][3], addr);
            }
#pragma unroll
            for (int gn = 0; gn < 8; gn++) {
                uint32_t b0, b1, b2, b3;
                int n  = gn * 16 + b_rowb;
                int ku = s * 2 + b_kx;
                uint32_t addr = bb + n * 128 + ((ku ^ (n & 7)) << 4);
                ldsm_x4(b0, b1, b2, b3, addr);
                mma_f16a(acc[0][gn * 2],     a[0][0], a[0][1], a[0][2], a[0][3], b0, b1);
                mma_f16a(acc[0][gn * 2 + 1], a[0][0], a[0][1], a[0][2], a[0][3], b2, b3);
                mma_f16a(acc[1][gn * 2],     a[1][0], a[1][1], a[1][2], a[1][3], b0, b1);
                mma_f16a(acc[1][gn * 2 + 1], a[1][0], a[1][1], a[1][2], a[1][3], b2, b3);
            }
        }

        if ((g & 7) == 7) {
            // tile epilogue: acc IS the score; no loads
            const int e0 = (g >> 3) * BN;
            const int c2 = (lane & 3) * 2;
#pragma unroll
            for (int af = 0; af < 2; af++)
#pragma unroll
                for (int f = 0; f < 16; f++) {
                    int col0 = e0 + f * 8 + c2;
#pragma unroll
                    for (int rh = 0; rh < 2; rh++) {
                        float2 c = __half22float2(*(__half2*)&acc[af][f][rh]);
                        t4_update(tp[af][rh], c.x, col0);
                        t4_update(tp[af][rh], c.y, col0 + 1);
                        acc[af][f][rh] = 0u;
                    }
                }
        }
        st = st + 1; if (st >= NSTG) st -= NSTG;
    }

    // merge top-4 across the 4 lanes sharing each row
#pragma unroll
    for (int af = 0; af < 2; af++)
#pragma unroll
        for (int rh = 0; rh < 2; rh++) {
#pragma unroll
            for (int o = 1; o < 4; o <<= 1) {
                float ov[4]; int oi[4];
#pragma unroll
                for (int k = 0; k < 4; k++) {
                    ov[k] = __shfl_xor_sync(0xffffffffu, tp[af][rh].v[k], o);
                    oi[k] = __shfl_xor_sync(0xffffffffu, tp[af][rh].i[k], o);
                }
#pragma unroll
                for (int k = 0; k < 4; k++) t4_update(tp[af][rh], ov[k], oi[k]);
            }
        }
    if ((lane & 3) == 0) {
#pragma unroll
        for (int af = 0; af < 2; af++)
#pragma unroll
            for (int rh = 0; rh < 2; rh++) {
                int r = row0 + wrow + af * 16 + rh * 8 + (lane >> 2);
#pragma unroll
                for (int k = 0; k < 4; k++) g_cand[r * 4 + k] = tp[af][rh].i[k];
            }
    }
}

// ---------------- exact fp32 re-score of top-4 candidates ----------------
__global__ void fixup_kernel(const float* __restrict__ z, const float* __restrict__ emb) {
    int row  = (blockIdx.x * blockDim.x + threadIdx.x) >> 5;
    int lane = threadIdx.x & 31;
    const float4* zr = (const float4*)(z + (size_t)row * D);
    float4 zf[4];
#pragma unroll
    for (int j = 0; j < 4; j++) zf[j] = zr[lane + j * 32];

    float bv = -INFINITY;
    int   bi = 0x7fffffff;
#pragma unroll
    for (int c = 0; c < 4; c++) {
        int e = g_cand[row * 4 + c];
        const float4* er = (const float4*)(emb + (size_t)e * D);
        float d = 0.0f;
#pragma unroll
        for (int j = 0; j < 4; j++) {
            float4 ev = er[lane + j * 32];
            d += zf[j].x * ev.x + zf[j].y * ev.y + zf[j].z * ev.z + zf[j].w * ev.w;
        }
        for (int o = 16; o; o >>= 1) d += __shfl_down_sync(0xffffffffu, d, o);
        if (lane == 0) {
            float s = d * g_inv[e];
            if (s > bv || (s == bv && e < bi)) { bv = s; bi = e; }
        }
    }
    if (lane == 0) g_idx[row] = bi;
}

// ---------------- gather + z_q_st + loss + counts + idx out ----------------
__global__ void gather_kernel(const float* __restrict__ z,
                              const float* __restrict__ emb,
                              float* __restrict__ out_zq,
                              float* __restrict__ out_idx) {
    __shared__ float sred[4];
    __shared__ float sbc;
    int n = blockIdx.x;
    int t = threadIdx.x;
    int e = g_idx[n];
    float inv_e = g_inv[e];

    float4 zv = ((const float4*)(z + (size_t)n * D))[t];
    float ss = zv.x * zv.x + zv.y * zv.y + zv.z * zv.z + zv.w * zv.w;
    for (int o = 16; o; o >>= 1) ss += __shfl_down_sync(0xffffffffu, ss, o);
    if ((t & 31) == 0) sred[t >> 5] = ss;
    __syncthreads();
    if (t == 0) sbc = sred[0] + sred[1] + sred[2] + sred[3];
    __syncthreads();
    float zinv = 1.0f / fmaxf(sqrtf(sbc), 1e-12f);

    float4 q = ((const float4*)(emb + (size_t)e * D))[t];
    q.x *= inv_e; q.y *= inv_e; q.z *= inv_e; q.w *= inv_e;

    float* o = out_zq + (size_t)n * D + t * 4;
    o[0] = q.x; o[1] = q.y; o[2] = q.z; o[3] = q.w;

    float dx = q.x - zv.x * zinv;
    float dy = q.y - zv.y * zinv;
    float dz = q.z - zv.z * zinv;
    float dw = q.w - zv.w * zinv;
    float ls = dx * dx + dy * dy + dz * dz + dw * dw;
    for (int o2 = 16; o2; o2 >>= 1) ls += __shfl_down_sync(0xffffffffu, ls, o2);
    if ((t & 31) == 0) sred[t >> 5] = ls;
    __syncthreads();
    if (t == 0) {
        atomicAdd(&g_loss, sred[0] + sred[1] + sred[2] + sred[3]);
        atomicAdd(&g_counts[e], 1.0f);
        out_idx[n] = (float)e;
    }
}

__global__ void finalize_kernel(float* __restrict__ out, int N) {
    __shared__ float sh[256];
    float h = 0.0f;
    float invN = 1.0f / (float)N;
    for (int i = threadIdx.x; i < NE; i += 256) {
        float p = g_counts[i] * invN;
        h -= p * logf(p + 1e-10f);
    }
    sh[threadIdx.x] = h;
    __syncthreads();
    for (int s = 128; s; s >>= 1) {
        if (threadIdx.x < s) sh[threadIdx.x] += sh[threadIdx.x + s];
        __syncthreads();
    }
    if (threadIdx.x == 0) {
        out[0] = g_loss * (1.0f + BETA) / ((float)N * (float)D);
        out[1 + (size_t)N * D + (size_t)N] = expf(sh[0]);
    }
}

// ---------------- launch ----------------
extern "C" void kernel_launch(void* const* d_in, const int* in_sizes, int n_in,
                              void* d_out, int out_size) {
    const float* z   = (const float*)d_in[0];
    const float* emb = (const float*)d_in[1];
    float* out = (float*)d_out;

    int ND = in_sizes[0];
    int N  = ND / D;            // 32768

    cudaFuncSetAttribute(mma_argmax_kernel,
                         cudaFuncAttributeMaxDynamicSharedMemorySize, SMEM_SZ);

    zero_kernel<<<(NE + 255) / 256, 256>>>();
    embprep_kernel<<<NE, 128>>>(emb);
    cvt_z_kernel<<<(N * D / 4) / 256, 256>>>(z);
    mma_argmax_kernel<<<N / BM, 256, SMEM_SZ>>>();
    fixup_kernel<<<N / 8, 256>>>(z, emb);
    // output layout (tuple order, all as float32):
    // [0] loss | [1 .. 1+N*D) z_q_st | [1+N*D .. 1+N*D+N) idx | [last] perplexity
    gather_kernel<<<N, 128>>>(z, emb, out + 1, out + 1 + (size_t)ND);
    finalize_kernel<<<1, 256>>>(out, N);
}